// round 2
// baseline (speedup 1.0000x reference)
#include <cuda_runtime.h>
#include <cuda_bf16.h>
#include <math.h>

// Problem constants (fixed shapes for this problem)
#define NN 100000      // nodes
#define NE 1000000     // edges
#define F0 58
#define F1 300
#define F2 100

// ---------------- device scratch (allocation-free rule: static globals) ----
__device__ int   g_deg[NN];
__device__ float g_dis[NN];
__device__ int   g_row[NE];
__device__ int   g_col[NE];
__device__ float g_norm[NE];
__device__ float g_agg1[(size_t)NN * F0];     // 23.2 MB
__device__ float g_h1  [(size_t)NN * F1];     // 120  MB
__device__ float g_h2p [(size_t)NN * F2];     // 40   MB
__device__ float g_agg2[(size_t)NN * F2];     // 40   MB
__device__ float g_h3p [NN];

// ---------------- degree / norm ----------------
__global__ void k_init_deg() {
    int v = blockIdx.x * blockDim.x + threadIdx.x;
    if (v < NN) g_deg[v] = 1;               // self-loop
}

// NOTE: edge_index is int32 on device (JAX x64 disabled coerces int64->int32)
__global__ void k_edge_prep(const int* __restrict__ ei) {
    int e = blockIdx.x * blockDim.x + threadIdx.x;
    if (e >= NE) return;
    int r = ei[e];
    int c = ei[NE + e];
    g_row[e] = r;
    g_col[e] = c;
    atomicAdd(&g_deg[c], 1);
}

__global__ void k_dis() {
    int v = blockIdx.x * blockDim.x + threadIdx.x;
    if (v < NN) g_dis[v] = rsqrtf((float)g_deg[v]);
}

__global__ void k_norm() {
    int e = blockIdx.x * blockDim.x + threadIdx.x;
    if (e < NE) g_norm[e] = g_dis[g_row[e]] * g_dis[g_col[e]];
}

// ---------------- aggregation ----------------
// dst[v,f] = dis[v]^2 * src[v,f]   (self-loop term, also serves as init)
__global__ void k_agg_init(const float* __restrict__ src, float* __restrict__ dst,
                           int F) {
    long long idx = (long long)blockIdx.x * blockDim.x + threadIdx.x;
    long long total = (long long)NN * F;
    if (idx >= total) return;
    int v = (int)(idx / F);
    float d = g_dis[v];
    dst[idx] = d * d * src[idx];
}

// warp per edge: dst[col,f] += norm * src[row,f]
__global__ void k_agg_edges(const float* __restrict__ src, float* __restrict__ dst,
                            int F) {
    int gtid = blockIdx.x * blockDim.x + threadIdx.x;
    int e    = gtid >> 5;
    int lane = gtid & 31;
    if (e >= NE) return;
    int r = g_row[e];
    int c = g_col[e];
    float nrm = g_norm[e];
    const float* s = src + (size_t)r * F;
    float*       d = dst + (size_t)c * F;
    for (int f = lane; f < F; f += 32)
        atomicAdd(&d[f], s[f] * nrm);
}

// ---------------- GEMM: C[M,N] = A[M,K] @ B[K,N] (+bias)(+relu) ----------
template <int BM, int BN, int BK, int TM, int TN, bool BIAS, bool RELU>
__global__ void k_gemm(const float* __restrict__ A, const float* __restrict__ B,
                       const float* __restrict__ bias, float* __restrict__ C,
                       int M, int N, int K) {
    __shared__ float As[BK][BM];
    __shared__ float Bs[BK][BN];
    const int NT  = (BM / TM) * (BN / TN);     // threads per block
    const int tid = threadIdx.x;
    const int tx  = tid % (BN / TN);
    const int ty  = tid / (BN / TN);
    const int brow = blockIdx.y * BM;
    const int bcol = blockIdx.x * BN;

    float acc[TM][TN];
    #pragma unroll
    for (int i = 0; i < TM; i++)
        #pragma unroll
        for (int j = 0; j < TN; j++) acc[i][j] = 0.f;

    for (int k0 = 0; k0 < K; k0 += BK) {
        #pragma unroll 4
        for (int i = tid; i < BM * BK; i += NT) {
            int m = i / BK, k = i % BK;
            int gm = brow + m, gk = k0 + k;
            As[k][m] = (gm < M && gk < K) ? A[(size_t)gm * K + gk] : 0.f;
        }
        #pragma unroll 4
        for (int i = tid; i < BK * BN; i += NT) {
            int k = i / BN, n = i % BN;
            int gk = k0 + k, gn = bcol + n;
            Bs[k][n] = (gk < K && gn < N) ? B[(size_t)gk * N + gn] : 0.f;
        }
        __syncthreads();

        #pragma unroll
        for (int k = 0; k < BK; k++) {
            float a[TM], b[TN];
            #pragma unroll
            for (int i = 0; i < TM; i++) a[i] = As[k][ty * TM + i];
            #pragma unroll
            for (int j = 0; j < TN; j++) b[j] = Bs[k][tx * TN + j];
            #pragma unroll
            for (int i = 0; i < TM; i++)
                #pragma unroll
                for (int j = 0; j < TN; j++) acc[i][j] += a[i] * b[j];
        }
        __syncthreads();
    }

    #pragma unroll
    for (int i = 0; i < TM; i++) {
        int gm = brow + ty * TM + i;
        if (gm >= M) continue;
        #pragma unroll
        for (int j = 0; j < TN; j++) {
            int gn = bcol + tx * TN + j;
            if (gn >= N) continue;
            float v = acc[i][j];
            if (BIAS) v += bias[gn];
            if (RELU) v = fmaxf(v, 0.f);
            C[(size_t)gm * N + gn] = v;
        }
    }
}

// ---------------- layer-3 fused dot: h3p[v] = relu(agg2[v,:]+b2) . W3 -----
__global__ void k_dot3(const float* __restrict__ b2, const float* __restrict__ W3) {
    int gtid = blockIdx.x * blockDim.x + threadIdx.x;
    int v    = gtid >> 5;
    int lane = gtid & 31;
    if (v >= NN) return;
    const float* a = g_agg2 + (size_t)v * F2;
    float s = 0.f;
    for (int f = lane; f < F2; f += 32)
        s += fmaxf(a[f] + b2[f], 0.f) * W3[f];
    #pragma unroll
    for (int o = 16; o > 0; o >>= 1)
        s += __shfl_xor_sync(0xffffffffu, s, o);
    if (lane == 0) g_h3p[v] = s;
}

// out[v] = dis^2 * h3p[v] + b3
__global__ void k_out_init(float* __restrict__ out, const float* __restrict__ b3) {
    int v = blockIdx.x * blockDim.x + threadIdx.x;
    if (v >= NN) return;
    float d = g_dis[v];
    out[v] = d * d * g_h3p[v] + b3[0];
}

__global__ void k_agg_edges3(float* __restrict__ out) {
    int e = blockIdx.x * blockDim.x + threadIdx.x;
    if (e >= NE) return;
    atomicAdd(&out[g_col[e]], g_norm[e] * g_h3p[g_row[e]]);
}

// ---------------- launch ----------------
extern "C" void kernel_launch(void* const* d_in, const int* in_sizes, int n_in,
                              void* d_out, int out_size) {
    const float* x  = (const float*)d_in[0];
    const int*   ei = (const int*)d_in[1];      // int32 (JAX coerces int64->int32)
    const float* W1 = (const float*)d_in[2];
    const float* b1 = (const float*)d_in[3];
    const float* W2 = (const float*)d_in[4];
    const float* b2 = (const float*)d_in[5];
    const float* W3 = (const float*)d_in[6];
    const float* b3 = (const float*)d_in[7];
    float* out = (float*)d_out;

    const int T = 256;
    float* agg1 = nullptr; cudaGetSymbolAddress((void**)&agg1, g_agg1);
    float* h1   = nullptr; cudaGetSymbolAddress((void**)&h1,   g_h1);
    float* h2p  = nullptr; cudaGetSymbolAddress((void**)&h2p,  g_h2p);
    float* agg2 = nullptr; cudaGetSymbolAddress((void**)&agg2, g_agg2);

    // degrees / norms
    k_init_deg<<<(NN + T - 1) / T, T>>>();
    k_edge_prep<<<(NE + T - 1) / T, T>>>(ei);
    k_dis<<<(NN + T - 1) / T, T>>>();
    k_norm<<<(NE + T - 1) / T, T>>>();

    // Layer 1: aggregate x (58 feats) first, then GEMM(+bias+relu)
    {
        long long tot = (long long)NN * F0;
        k_agg_init<<<(unsigned)((tot + T - 1) / T), T>>>(x, agg1, F0);
        long long warps = (long long)NE;
        k_agg_edges<<<(unsigned)((warps * 32 + T - 1) / T), T>>>(x, agg1, F0);
        dim3 grid((F1 + 63) / 64, (NN + 63) / 64);
        k_gemm<64, 64, 16, 4, 4, true, true>
            <<<grid, 256>>>(agg1, W1, b1, h1, NN, F1, F0);
    }

    // Layer 2: GEMM first (300->100), then aggregate 100 feats
    {
        dim3 grid((F2 + 63) / 64, (NN + 63) / 64);
        k_gemm<64, 64, 16, 4, 4, false, false>
            <<<grid, 256>>>(h1, W2, nullptr, h2p, NN, F2, F1);
        long long tot = (long long)NN * F2;
        k_agg_init<<<(unsigned)((tot + T - 1) / T), T>>>(h2p, agg2, F2);
        long long warps = (long long)NE;
        k_agg_edges<<<(unsigned)((warps * 32 + T - 1) / T), T>>>(h2p, agg2, F2);
    }

    // Layer 3: fused bias2+relu+dot(W3), then scalar aggregation
    {
        long long warps = (long long)NN;
        k_dot3<<<(unsigned)((warps * 32 + T - 1) / T), T>>>(b2, W3);
        k_out_init<<<(NN + T - 1) / T, T>>>(out, b3);
        k_agg_edges3<<<(NE + T - 1) / T, T>>>(out);
    }
    (void)in_sizes; (void)n_in; (void)out_size;
}

// round 3
// speedup vs baseline: 1.2382x; 1.2382x over previous
#include <cuda_runtime.h>
#include <cuda_bf16.h>
#include <math.h>

#define NN 100000      // nodes
#define NE 1000000     // edges
#define F0 58
#define F1 300
#define F2 100

// ---------------- device scratch (allocation-free rule: static globals) ----
__device__ int   g_indeg[NN];
__device__ float g_dis[NN];
__device__ int   g_row[NE];
__device__ int   g_col[NE];
__device__ int   g_soff[NN + 1];
__device__ int   g_cursor[NN];
__device__ uint2 g_sedge[NE];                  // packed {row_bits, norm_bits}
__device__ float g_agg1[(size_t)NN * F0];      // 23.2 MB
__device__ float g_h1  [(size_t)NN * F1];      // 120  MB
__device__ float g_h2p [(size_t)NN * F2];      // 40   MB
__device__ float g_agg2[(size_t)NN * F2];      // 40   MB
__device__ float g_h3p [NN];

// ---------------- graph prep ----------------
__global__ void k_zero_indeg() {
    int v = blockIdx.x * blockDim.x + threadIdx.x;
    if (v < NN) g_indeg[v] = 0;
}

// edge_index is int32 on device (JAX x64 disabled coerces int64->int32)
__global__ void k_edge_prep(const int* __restrict__ ei) {
    int e = blockIdx.x * blockDim.x + threadIdx.x;
    if (e >= NE) return;
    int r = ei[e];
    int c = ei[NE + e];
    g_row[e] = r;
    g_col[e] = c;
    atomicAdd(&g_indeg[c], 1);
}

__global__ void k_dis() {
    int v = blockIdx.x * blockDim.x + threadIdx.x;
    if (v < NN) g_dis[v] = rsqrtf((float)(g_indeg[v] + 1));   // +1 self-loop
}

// single-block exclusive scan of g_indeg -> g_soff (1024 threads)
__global__ void k_scan() {
    __shared__ int warp_sums[32];
    __shared__ int s_carry;
    const int tid = threadIdx.x;
    if (tid == 0) s_carry = 0;
    __syncthreads();
    for (int base = 0; base < NN; base += 1024) {
        int v = base + tid;
        int val = (v < NN) ? g_indeg[v] : 0;
        int x = val;
        #pragma unroll
        for (int o = 1; o < 32; o <<= 1) {
            int y = __shfl_up_sync(0xffffffffu, x, o);
            if ((tid & 31) >= o) x += y;
        }
        if ((tid & 31) == 31) warp_sums[tid >> 5] = x;
        __syncthreads();
        if (tid < 32) {
            int y = warp_sums[tid];
            #pragma unroll
            for (int o = 1; o < 32; o <<= 1) {
                int z = __shfl_up_sync(0xffffffffu, y, o);
                if (tid >= o) y += z;
            }
            warp_sums[tid] = y;
        }
        __syncthreads();
        int warp_prefix = (tid >= 32) ? warp_sums[(tid >> 5) - 1] : 0;
        int excl = x + warp_prefix - val;
        if (v < NN) g_soff[v] = s_carry + excl;
        int total = warp_sums[31];
        __syncthreads();
        if (tid == 0) s_carry += total;
        __syncthreads();
    }
    if (tid == 0) g_soff[NN] = s_carry;
}

__global__ void k_cursor_init() {
    int v = blockIdx.x * blockDim.x + threadIdx.x;
    if (v < NN) g_cursor[v] = g_soff[v];
}

__global__ void k_scatter() {
    int e = blockIdx.x * blockDim.x + threadIdx.x;
    if (e >= NE) return;
    int r = g_row[e];
    int c = g_col[e];
    int pos = atomicAdd(&g_cursor[c], 1);
    float nrm = g_dis[r] * g_dis[c];
    g_sedge[pos] = make_uint2((unsigned)r, __float_as_uint(nrm));
}

// ---------------- CSR aggregation: dst[v,:] = dis^2*src[v,:] + sum edges ----
template <int F>
__global__ void k_agg_csr(const float* __restrict__ src, float* __restrict__ dst) {
    int gtid = blockIdx.x * blockDim.x + threadIdx.x;
    int v    = gtid >> 5;
    int lane = gtid & 31;
    if (v >= NN) return;

    constexpr int NA = (F + 31) / 32;
    float acc[NA];
    float d = g_dis[v];
    const float* selfp = src + (size_t)v * F;
    #pragma unroll
    for (int i = 0; i < NA; i++) {
        int f = lane + 32 * i;
        acc[i] = (f < F) ? d * d * selfp[f] : 0.f;
    }

    int b  = g_soff[v];
    int e2 = g_soff[v + 1];
    for (int j = b; j < e2; j++) {
        uint2 pe = g_sedge[j];
        const float* sp = src + (size_t)pe.x * F;
        float w = __uint_as_float(pe.y);
        #pragma unroll
        for (int i = 0; i < NA; i++) {
            int f = lane + 32 * i;
            if (f < F) acc[i] += w * sp[f];
        }
    }

    float* dp = dst + (size_t)v * F;
    #pragma unroll
    for (int i = 0; i < NA; i++) {
        int f = lane + 32 * i;
        if (f < F) dp[f] = acc[i];
    }
}

// ---------------- GEMM: C[M,N] = A[M,K] @ B[K,N] (+bias)(+relu) ----------
template <int BM, int BN, int BK, int TM, int TN, bool BIAS, bool RELU>
__global__ void k_gemm(const float* __restrict__ A, const float* __restrict__ B,
                       const float* __restrict__ bias, float* __restrict__ C,
                       int M, int N, int K) {
    __shared__ float As[BK][BM];
    __shared__ float Bs[BK][BN];
    const int NT  = (BM / TM) * (BN / TN);
    const int tid = threadIdx.x;
    const int tx  = tid % (BN / TN);
    const int ty  = tid / (BN / TN);
    const int brow = blockIdx.y * BM;
    const int bcol = blockIdx.x * BN;

    float acc[TM][TN];
    #pragma unroll
    for (int i = 0; i < TM; i++)
        #pragma unroll
        for (int j = 0; j < TN; j++) acc[i][j] = 0.f;

    for (int k0 = 0; k0 < K; k0 += BK) {
        #pragma unroll 4
        for (int i = tid; i < BM * BK; i += NT) {
            int m = i / BK, k = i % BK;
            int gm = brow + m, gk = k0 + k;
            As[k][m] = (gm < M && gk < K) ? A[(size_t)gm * K + gk] : 0.f;
        }
        #pragma unroll 4
        for (int i = tid; i < BK * BN; i += NT) {
            int k = i / BN, n = i % BN;
            int gk = k0 + k, gn = bcol + n;
            Bs[k][n] = (gk < K && gn < N) ? B[(size_t)gk * N + gn] : 0.f;
        }
        __syncthreads();

        #pragma unroll
        for (int k = 0; k < BK; k++) {
            float a[TM], b[TN];
            #pragma unroll
            for (int i = 0; i < TM; i++) a[i] = As[k][ty * TM + i];
            #pragma unroll
            for (int j = 0; j < TN; j++) b[j] = Bs[k][tx * TN + j];
            #pragma unroll
            for (int i = 0; i < TM; i++)
                #pragma unroll
                for (int j = 0; j < TN; j++) acc[i][j] += a[i] * b[j];
        }
        __syncthreads();
    }

    #pragma unroll
    for (int i = 0; i < TM; i++) {
        int gm = brow + ty * TM + i;
        if (gm >= M) continue;
        #pragma unroll
        for (int j = 0; j < TN; j++) {
            int gn = bcol + tx * TN + j;
            if (gn >= N) continue;
            float v = acc[i][j];
            if (BIAS) v += bias[gn];
            if (RELU) v = fmaxf(v, 0.f);
            C[(size_t)gm * N + gn] = v;
        }
    }
}

// ---------------- layer-3 fused dot: h3p[v] = relu(agg2[v,:]+b2) . W3 -----
__global__ void k_dot3(const float* __restrict__ b2, const float* __restrict__ W3) {
    int gtid = blockIdx.x * blockDim.x + threadIdx.x;
    int v    = gtid >> 5;
    int lane = gtid & 31;
    if (v >= NN) return;
    const float* a = g_agg2 + (size_t)v * F2;
    float s = 0.f;
    for (int f = lane; f < F2; f += 32)
        s += fmaxf(a[f] + b2[f], 0.f) * W3[f];
    #pragma unroll
    for (int o = 16; o > 0; o >>= 1)
        s += __shfl_xor_sync(0xffffffffu, s, o);
    if (lane == 0) g_h3p[v] = s;
}

// out[v] = dis^2*h3p[v] + sum_in norm*h3p[row] + b3   (CSR, no atomics)
__global__ void k_out_csr(float* __restrict__ out, const float* __restrict__ b3) {
    int v = blockIdx.x * blockDim.x + threadIdx.x;
    if (v >= NN) return;
    float d = g_dis[v];
    float s = d * d * g_h3p[v];
    int b  = g_soff[v];
    int e2 = g_soff[v + 1];
    for (int j = b; j < e2; j++) {
        uint2 pe = g_sedge[j];
        s += __uint_as_float(pe.y) * g_h3p[pe.x];
    }
    out[v] = s + b3[0];
}

// ---------------- launch ----------------
extern "C" void kernel_launch(void* const* d_in, const int* in_sizes, int n_in,
                              void* d_out, int out_size) {
    const float* x  = (const float*)d_in[0];
    const int*   ei = (const int*)d_in[1];
    const float* W1 = (const float*)d_in[2];
    const float* b1 = (const float*)d_in[3];
    const float* W2 = (const float*)d_in[4];
    const float* b2 = (const float*)d_in[5];
    const float* W3 = (const float*)d_in[6];
    const float* b3 = (const float*)d_in[7];
    float* out = (float*)d_out;

    const int T = 256;
    float* agg1 = nullptr; cudaGetSymbolAddress((void**)&agg1, g_agg1);
    float* h1   = nullptr; cudaGetSymbolAddress((void**)&h1,   g_h1);
    float* h2p  = nullptr; cudaGetSymbolAddress((void**)&h2p,  g_h2p);
    float* agg2 = nullptr; cudaGetSymbolAddress((void**)&agg2, g_agg2);

    // CSR build
    k_zero_indeg<<<(NN + T - 1) / T, T>>>();
    k_edge_prep<<<(NE + T - 1) / T, T>>>(ei);
    k_dis<<<(NN + T - 1) / T, T>>>();
    k_scan<<<1, 1024>>>();
    k_cursor_init<<<(NN + T - 1) / T, T>>>();
    k_scatter<<<(NE + T - 1) / T, T>>>();

    const unsigned aggGrid = (unsigned)(((long long)NN * 32 + T - 1) / T);

    // Layer 1: aggregate x (58 feats) first, then GEMM(+bias+relu)
    k_agg_csr<F0><<<aggGrid, T>>>(x, agg1);
    {
        dim3 grid((F1 + 63) / 64, (NN + 63) / 64);
        k_gemm<64, 64, 16, 4, 4, true, true>
            <<<grid, 256>>>(agg1, W1, b1, h1, NN, F1, F0);
    }

    // Layer 2: GEMM first (300->100), then aggregate 100 feats
    {
        dim3 grid((F2 + 63) / 64, (NN + 63) / 64);
        k_gemm<64, 64, 16, 4, 4, false, false>
            <<<grid, 256>>>(h1, W2, nullptr, h2p, NN, F2, F1);
    }
    k_agg_csr<F2><<<aggGrid, T>>>(h2p, agg2);

    // Layer 3: fused bias2+relu+dot(W3), then CSR aggregation to output
    k_dot3<<<aggGrid, T>>>(b2, W3);
    k_out_csr<<<(NN + T - 1) / T, T>>>(out, b3);

    (void)in_sizes; (void)n_in; (void)out_size;
}

// round 4
// speedup vs baseline: 1.5344x; 1.2392x over previous
#include <cuda_runtime.h>
#include <cuda_bf16.h>
#include <math.h>

#define NN 100000      // nodes
#define NE 1000000     // edges
#define F0 58
#define F1 300
#define F2 100
#define NB 98          // ceil(NN / 1024) scan blocks

// ---------------- device scratch (allocation-free rule: static globals) ----
__device__ int   g_indeg[NN];
__device__ float g_dis[NN];
__device__ int   g_row[NE];
__device__ int   g_col[NE];
__device__ int   g_soff[NN + 1];
__device__ int   g_cursor[NN];
__device__ int   g_bsum[NB];
__device__ uint2 g_sedge[NE];                  // packed {row_bits, norm_bits}
__device__ float g_agg1[(size_t)NN * F0];      // 23.2 MB
__device__ float g_h1  [(size_t)NN * F1];      // 120  MB
__device__ float g_h2p [(size_t)NN * F2];      // 40   MB
__device__ float g_agg2[(size_t)NN * F2];      // 40   MB
__device__ float g_h3p [NN];

// ---------------- graph prep ----------------
__global__ void k_zero_indeg() {
    int v = blockIdx.x * blockDim.x + threadIdx.x;
    if (v < NN) g_indeg[v] = 0;
}

// edge_index is int32 on device (JAX x64 disabled coerces int64->int32)
__global__ void k_edge_prep(const int* __restrict__ ei) {
    int e = blockIdx.x * blockDim.x + threadIdx.x;
    if (e >= NE) return;
    int r = ei[e];
    int c = ei[NE + e];
    g_row[e] = r;
    g_col[e] = c;
    atomicAdd(&g_indeg[c], 1);
}

__global__ void k_dis() {
    int v = blockIdx.x * blockDim.x + threadIdx.x;
    if (v < NN) g_dis[v] = rsqrtf((float)(g_indeg[v] + 1));   // +1 self-loop
}

// phase 1: per-block local exclusive scan (1024 elems/block) + block total
__global__ void k_scan_local() {
    __shared__ int warp_sums[32];
    const int tid = threadIdx.x;
    const int v = blockIdx.x * 1024 + tid;
    int val = (v < NN) ? g_indeg[v] : 0;
    int x = val;
    #pragma unroll
    for (int o = 1; o < 32; o <<= 1) {
        int y = __shfl_up_sync(0xffffffffu, x, o);
        if ((tid & 31) >= o) x += y;
    }
    if ((tid & 31) == 31) warp_sums[tid >> 5] = x;
    __syncthreads();
    if (tid < 32) {
        int y = warp_sums[tid];
        #pragma unroll
        for (int o = 1; o < 32; o <<= 1) {
            int z = __shfl_up_sync(0xffffffffu, y, o);
            if (tid >= o) y += z;
        }
        warp_sums[tid] = y;
    }
    __syncthreads();
    int warp_prefix = (tid >= 32) ? warp_sums[(tid >> 5) - 1] : 0;
    if (v < NN) g_soff[v] = x + warp_prefix - val;   // local exclusive
    if (tid == 0) g_bsum[blockIdx.x] = warp_sums[31];
}

// phase 2: tiny exclusive scan of NB block sums (+ grand total to g_soff[NN])
__global__ void k_scan_bsum() {
    if (threadIdx.x == 0) {
        int run = 0;
        for (int b = 0; b < NB; b++) {
            int t = g_bsum[b];
            g_bsum[b] = run;
            run += t;
        }
        g_soff[NN] = run;
    }
}

// phase 3: add block offsets; init cursors
__global__ void k_scan_add() {
    int v = blockIdx.x * 1024 + threadIdx.x;
    if (v >= NN) return;
    int s = g_soff[v] + g_bsum[blockIdx.x];
    g_soff[v] = s;
    g_cursor[v] = s;
}

__global__ void k_scatter() {
    int e = blockIdx.x * blockDim.x + threadIdx.x;
    if (e >= NE) return;
    int r = g_row[e];
    int c = g_col[e];
    int pos = atomicAdd(&g_cursor[c], 1);
    float nrm = g_dis[r] * g_dis[c];
    g_sedge[pos] = make_uint2((unsigned)r, __float_as_uint(nrm));
}

// ---------------- CSR aggregation: dst[v,:] = dis^2*src[v,:] + sum edges ----
template <int F>
__global__ void k_agg_csr(const float* __restrict__ src, float* __restrict__ dst) {
    int gtid = blockIdx.x * blockDim.x + threadIdx.x;
    int v    = gtid >> 5;
    int lane = gtid & 31;
    if (v >= NN) return;

    constexpr int NA = (F + 31) / 32;
    float acc[NA];
    float d = g_dis[v];
    const float* selfp = src + (size_t)v * F;
    #pragma unroll
    for (int i = 0; i < NA; i++) {
        int f = lane + 32 * i;
        acc[i] = (f < F) ? d * d * selfp[f] : 0.f;
    }

    int b  = g_soff[v];
    int e2 = g_soff[v + 1];
    for (int j = b; j < e2; j++) {
        uint2 pe = g_sedge[j];
        const float* sp = src + (size_t)pe.x * F;
        float w = __uint_as_float(pe.y);
        #pragma unroll
        for (int i = 0; i < NA; i++) {
            int f = lane + 32 * i;
            if (f < F) acc[i] += w * sp[f];
        }
    }

    float* dp = dst + (size_t)v * F;
    #pragma unroll
    for (int i = 0; i < NA; i++) {
        int f = lane + 32 * i;
        if (f < F) dp[f] = acc[i];
    }
}

// ---------------- GEMM with packed f32x2 FMA (FFMA2) ----------------------
// C[M,N] = A[M,K] @ B[K,N] (+bias)(+relu)
// Accumulators packed along M (pairs of rows). B tile stored in smem as
// duplicated (b,b) u64 pairs, word-swizzled for conflict-free LDS.64.
#define FMA2(d, a, b) \
    asm("fma.rn.f32x2 %0, %1, %2, %0;" : "+l"(d) : "l"(a), "l"(b))

template <int BM, int BN, int BK, int TM, int TN, bool BIAS, bool RELU>
__global__ void __launch_bounds__(256, 2)
k_gemm2(const float* __restrict__ A, const float* __restrict__ B,
        const float* __restrict__ bias, float* __restrict__ C,
        int M, int N, int K) {
    __shared__ __align__(16) float As[BK][BM + 2];   // +2 keeps rows 8B-aligned, banks clean
    __shared__ unsigned long long Bs2[BK][BN];       // duplicated pairs, swizzled
    const int tid = threadIdx.x;
    const int tx  = tid % (BN / TN);
    const int ty  = tid / (BN / TN);
    const int brow = blockIdx.y * BM;
    const int bcol = blockIdx.x * BN;

    unsigned long long acc[TM / 2][TN];
    #pragma unroll
    for (int i = 0; i < TM / 2; i++)
        #pragma unroll
        for (int j = 0; j < TN; j++) acc[i][j] = 0ull;

    for (int k0 = 0; k0 < K; k0 += BK) {
        // fill As (coalesced global read; conflict-free strided smem write)
        #pragma unroll 4
        for (int i = tid; i < BM * BK; i += 256) {
            int m = i / BK, k = i % BK;
            int gm = brow + m, gk = k0 + k;
            As[k][m] = (gm < M && gk < K) ? A[(size_t)gm * K + gk] : 0.f;
        }
        // fill Bs2: duplicate each B value into a u64 pair; swizzle words so
        // thread-column loads are conflict-free: w(n) = (n>>2) + (n&3)*(BN/4)
        #pragma unroll 4
        for (int i = tid; i < BK * BN; i += 256) {
            int k = i / BN, n = i % BN;
            int gk = k0 + k, gn = bcol + n;
            float bv = (gk < K && gn < N) ? B[(size_t)gk * N + gn] : 0.f;
            unsigned u = __float_as_uint(bv);
            Bs2[k][(n >> 2) + (n & 3) * (BN / 4)] =
                ((unsigned long long)u << 32) | u;
        }
        __syncthreads();

        #pragma unroll
        for (int k = 0; k < BK; k++) {
            unsigned long long a2[TM / 2], b2[TN];
            #pragma unroll
            for (int i = 0; i < TM / 2; i++)
                a2[i] = *(const unsigned long long*)&As[k][ty * TM + 2 * i];
            #pragma unroll
            for (int j = 0; j < TN; j++) {
                int n = tx * TN + j;
                b2[j] = Bs2[k][(n >> 2) + (n & 3) * (BN / 4)];
            }
            #pragma unroll
            for (int i = 0; i < TM / 2; i++)
                #pragma unroll
                for (int j = 0; j < TN; j++)
                    FMA2(acc[i][j], a2[i], b2[j]);
        }
        __syncthreads();
    }

    #pragma unroll
    for (int i = 0; i < TM / 2; i++) {
        int gm0 = brow + ty * TM + 2 * i;
        #pragma unroll
        for (int j = 0; j < TN; j++) {
            int gn = bcol + tx * TN + j;
            if (gn >= N) continue;
            float lo = __uint_as_float((unsigned)(acc[i][j] & 0xffffffffull));
            float hi = __uint_as_float((unsigned)(acc[i][j] >> 32));
            if (BIAS) { float bb = bias[gn]; lo += bb; hi += bb; }
            if (RELU) { lo = fmaxf(lo, 0.f); hi = fmaxf(hi, 0.f); }
            if (gm0 < M)     C[(size_t)gm0 * N + gn]       = lo;
            if (gm0 + 1 < M) C[(size_t)(gm0 + 1) * N + gn] = hi;
        }
    }
}

// ---------------- layer-3 fused dot: h3p[v] = relu(agg2[v,:]+b2) . W3 -----
__global__ void k_dot3(const float* __restrict__ b2, const float* __restrict__ W3) {
    int gtid = blockIdx.x * blockDim.x + threadIdx.x;
    int v    = gtid >> 5;
    int lane = gtid & 31;
    if (v >= NN) return;
    const float* a = g_agg2 + (size_t)v * F2;
    float s = 0.f;
    for (int f = lane; f < F2; f += 32)
        s += fmaxf(a[f] + b2[f], 0.f) * W3[f];
    #pragma unroll
    for (int o = 16; o > 0; o >>= 1)
        s += __shfl_xor_sync(0xffffffffu, s, o);
    if (lane == 0) g_h3p[v] = s;
}

// out[v] = dis^2*h3p[v] + sum_in norm*h3p[row] + b3   (CSR, no atomics)
__global__ void k_out_csr(float* __restrict__ out, const float* __restrict__ b3) {
    int v = blockIdx.x * blockDim.x + threadIdx.x;
    if (v >= NN) return;
    float d = g_dis[v];
    float s = d * d * g_h3p[v];
    int b  = g_soff[v];
    int e2 = g_soff[v + 1];
    for (int j = b; j < e2; j++) {
        uint2 pe = g_sedge[j];
        s += __uint_as_float(pe.y) * g_h3p[pe.x];
    }
    out[v] = s + b3[0];
}

// ---------------- launch ----------------
extern "C" void kernel_launch(void* const* d_in, const int* in_sizes, int n_in,
                              void* d_out, int out_size) {
    const float* x  = (const float*)d_in[0];
    const int*   ei = (const int*)d_in[1];
    const float* W1 = (const float*)d_in[2];
    const float* b1 = (const float*)d_in[3];
    const float* W2 = (const float*)d_in[4];
    const float* b2 = (const float*)d_in[5];
    const float* W3 = (const float*)d_in[6];
    const float* b3 = (const float*)d_in[7];
    float* out = (float*)d_out;

    const int T = 256;
    float* agg1 = nullptr; cudaGetSymbolAddress((void**)&agg1, g_agg1);
    float* h1   = nullptr; cudaGetSymbolAddress((void**)&h1,   g_h1);
    float* h2p  = nullptr; cudaGetSymbolAddress((void**)&h2p,  g_h2p);
    float* agg2 = nullptr; cudaGetSymbolAddress((void**)&agg2, g_agg2);

    // CSR build (parallel 3-phase scan)
    k_zero_indeg<<<(NN + T - 1) / T, T>>>();
    k_edge_prep<<<(NE + T - 1) / T, T>>>(ei);
    k_dis<<<(NN + T - 1) / T, T>>>();
    k_scan_local<<<NB, 1024>>>();
    k_scan_bsum<<<1, 32>>>();
    k_scan_add<<<NB, 1024>>>();
    k_scatter<<<(NE + T - 1) / T, T>>>();

    const unsigned aggGrid = (unsigned)(((long long)NN * 32 + T - 1) / T);

    // Layer 1: aggregate x (58 feats) first, then GEMM(+bias+relu)
    k_agg_csr<F0><<<aggGrid, T>>>(x, agg1);
    {
        dim3 grid((F1 + 63) / 64, (NN + 127) / 128);
        k_gemm2<128, 64, 16, 8, 4, true, true>
            <<<grid, 256>>>(agg1, W1, b1, h1, NN, F1, F0);
    }

    // Layer 2: GEMM first (300->100), then aggregate 100 feats
    {
        dim3 grid(1, (NN + 127) / 128);   // N=100 fits one 128-col block
        k_gemm2<128, 128, 16, 8, 8, false, false>
            <<<grid, 256>>>(h1, W2, nullptr, h2p, NN, F2, F1);
    }
    k_agg_csr<F2><<<aggGrid, T>>>(h2p, agg2);

    // Layer 3: fused bias2+relu+dot(W3), then CSR aggregation to output
    k_dot3<<<aggGrid, T>>>(b2, W3);
    k_out_csr<<<(NN + T - 1) / T, T>>>(out, b3);

    (void)in_sizes; (void)n_in; (void)out_size;
}

// round 5
// speedup vs baseline: 1.6483x; 1.0743x over previous
#include <cuda_runtime.h>
#include <cuda_bf16.h>
#include <math.h>

#define NN 100000      // nodes
#define NE 1000000     // edges
#define F0 58
#define F1 300
#define F2 100
#define NB 98          // ceil(NN / 1024) scan blocks

// ---------------- device scratch (allocation-free rule: static globals) ----
__device__ int   g_indeg[NN];
__device__ float g_dis[NN];
__device__ int   g_row[NE];
__device__ int   g_col[NE];
__device__ int   g_soff[NN + 1];
__device__ int   g_cursor[NN];
__device__ int   g_bsum[NB];
__device__ uint2 g_sedge[NE];                  // packed {row_bits, norm_bits}
__device__ float g_agg1[(size_t)NN * F0];      // 23.2 MB
__device__ float g_h1  [(size_t)NN * F1];      // 120  MB
__device__ float g_h2p [(size_t)NN * F2];      // 40   MB
__device__ float g_agg2[(size_t)NN * F2];      // 40   MB
__device__ float g_h3p [NN];

// ---------------- graph prep ----------------
__global__ void k_zero_indeg() {
    int v = blockIdx.x * blockDim.x + threadIdx.x;
    if (v < NN) g_indeg[v] = 0;
}

// edge_index is int32 on device (JAX x64 disabled coerces int64->int32)
__global__ void k_edge_prep(const int* __restrict__ ei) {
    int e = blockIdx.x * blockDim.x + threadIdx.x;
    if (e >= NE) return;
    int r = ei[e];
    int c = ei[NE + e];
    g_row[e] = r;
    g_col[e] = c;
    atomicAdd(&g_indeg[c], 1);
}

__global__ void k_dis() {
    int v = blockIdx.x * blockDim.x + threadIdx.x;
    if (v < NN) g_dis[v] = rsqrtf((float)(g_indeg[v] + 1));   // +1 self-loop
}

// phase 1: per-block local exclusive scan (1024 elems/block) + block total
__global__ void k_scan_local() {
    __shared__ int warp_sums[32];
    const int tid = threadIdx.x;
    const int v = blockIdx.x * 1024 + tid;
    int val = (v < NN) ? g_indeg[v] : 0;
    int x = val;
    #pragma unroll
    for (int o = 1; o < 32; o <<= 1) {
        int y = __shfl_up_sync(0xffffffffu, x, o);
        if ((tid & 31) >= o) x += y;
    }
    if ((tid & 31) == 31) warp_sums[tid >> 5] = x;
    __syncthreads();
    if (tid < 32) {
        int y = warp_sums[tid];
        #pragma unroll
        for (int o = 1; o < 32; o <<= 1) {
            int z = __shfl_up_sync(0xffffffffu, y, o);
            if (tid >= o) y += z;
        }
        warp_sums[tid] = y;
    }
    __syncthreads();
    int warp_prefix = (tid >= 32) ? warp_sums[(tid >> 5) - 1] : 0;
    if (v < NN) g_soff[v] = x + warp_prefix - val;   // local exclusive
    if (tid == 0) g_bsum[blockIdx.x] = warp_sums[31];
}

// phase 2: tiny exclusive scan of NB block sums (+ grand total to g_soff[NN])
__global__ void k_scan_bsum() {
    if (threadIdx.x == 0) {
        int run = 0;
        for (int b = 0; b < NB; b++) {
            int t = g_bsum[b];
            g_bsum[b] = run;
            run += t;
        }
        g_soff[NN] = run;
    }
}

// phase 3: add block offsets; init cursors
__global__ void k_scan_add() {
    int v = blockIdx.x * 1024 + threadIdx.x;
    if (v >= NN) return;
    int s = g_soff[v] + g_bsum[blockIdx.x];
    g_soff[v] = s;
    g_cursor[v] = s;
}

__global__ void k_scatter() {
    int e = blockIdx.x * blockDim.x + threadIdx.x;
    if (e >= NE) return;
    int r = g_row[e];
    int c = g_col[e];
    int pos = atomicAdd(&g_cursor[c], 1);
    float nrm = g_dis[r] * g_dis[c];
    g_sedge[pos] = make_uint2((unsigned)r, __float_as_uint(nrm));
}

// ---------------- CSR aggregation: dst[v,:] = dis^2*src[v,:] + sum edges ----
template <int F>
__global__ void k_agg_csr(const float* __restrict__ src, float* __restrict__ dst) {
    int gtid = blockIdx.x * blockDim.x + threadIdx.x;
    int v    = gtid >> 5;
    int lane = gtid & 31;
    if (v >= NN) return;

    constexpr int NA = (F + 31) / 32;
    float acc[NA];
    float d = g_dis[v];
    const float* selfp = src + (size_t)v * F;
    #pragma unroll
    for (int i = 0; i < NA; i++) {
        int f = lane + 32 * i;
        acc[i] = (f < F) ? d * d * selfp[f] : 0.f;
    }

    int b  = g_soff[v];
    int e2 = g_soff[v + 1];
    for (int j = b; j < e2; j++) {
        uint2 pe = g_sedge[j];
        const float* sp = src + (size_t)pe.x * F;
        float w = __uint_as_float(pe.y);
        #pragma unroll
        for (int i = 0; i < NA; i++) {
            int f = lane + 32 * i;
            if (f < F) acc[i] += w * sp[f];
        }
    }

    float* dp = dst + (size_t)v * F;
    #pragma unroll
    for (int i = 0; i < NA; i++) {
        int f = lane + 32 * i;
        if (f < F) dp[f] = acc[i];
    }
}

// ---------------- GEMM with packed f32x2 FMA (FFMA2) ----------------------
// C[M,N] = A[M,K] @ B[K,N] (+bias)(+relu)
// Accumulators packed along M (pairs of rows -> LDS.64 A fragments).
// B stored SCALAR in smem (word-swizzled); duplicated into f32x2 pairs in
// registers (ALU pipe) so smem traffic is 2.0 flop/byte — balanced against
// the FFMA2 fma-pipe rate (256 flop/cyc/SM vs 128 B/cyc/SM crossbar).
#define FMA2(d, a, b) \
    asm("fma.rn.f32x2 %0, %1, %2, %0;" : "+l"(d) : "l"(a), "l"(b))
#define PACK2(d, s) \
    asm("mov.b64 %0, {%1, %1};" : "=l"(d) : "r"(s))

template <int BM, int BN, int BK, int TM, int TN, int NT, bool BIAS, bool RELU>
__global__ void __launch_bounds__(NT, 2)
k_gemm2(const float* __restrict__ A, const float* __restrict__ B,
        const float* __restrict__ bias, float* __restrict__ C,
        int M, int N, int K) {
    __shared__ __align__(16) float As[BK][BM + 2];
    __shared__ float Bs[BK][BN];                 // scalar, word-swizzled
    const int tid = threadIdx.x;
    const int tx  = tid % (BN / TN);
    const int ty  = tid / (BN / TN);
    const int brow = blockIdx.y * BM;
    const int bcol = blockIdx.x * BN;

    unsigned long long acc[TM / 2][TN];
    #pragma unroll
    for (int i = 0; i < TM / 2; i++)
        #pragma unroll
        for (int j = 0; j < TN; j++) acc[i][j] = 0ull;

    for (int k0 = 0; k0 < K; k0 += BK) {
        #pragma unroll 4
        for (int i = tid; i < BM * BK; i += NT) {
            int m = i / BK, k = i % BK;
            int gm = brow + m, gk = k0 + k;
            As[k][m] = (gm < M && gk < K) ? A[(size_t)gm * K + gk] : 0.f;
        }
        // swizzle: w(n) = (n>>2) + (n&3)*(BN/4) — per-j warp loads bank-clean
        #pragma unroll 4
        for (int i = tid; i < BK * BN; i += NT) {
            int k = i / BN, n = i % BN;
            int gk = k0 + k, gn = bcol + n;
            Bs[k][(n >> 2) + (n & 3) * (BN / 4)] =
                (gk < K && gn < N) ? B[(size_t)gk * N + gn] : 0.f;
        }
        __syncthreads();

        #pragma unroll
        for (int k = 0; k < BK; k++) {
            unsigned long long a2[TM / 2], b2[TN];
            #pragma unroll
            for (int i = 0; i < TM / 2; i++)
                a2[i] = *(const unsigned long long*)&As[k][ty * TM + 2 * i];
            #pragma unroll
            for (int j = 0; j < TN; j++) {
                int n = tx * TN + j;
                unsigned bv = __float_as_uint(Bs[k][(n >> 2) + (n & 3) * (BN / 4)]);
                PACK2(b2[j], bv);
            }
            #pragma unroll
            for (int i = 0; i < TM / 2; i++)
                #pragma unroll
                for (int j = 0; j < TN; j++)
                    FMA2(acc[i][j], a2[i], b2[j]);
        }
        __syncthreads();
    }

    #pragma unroll
    for (int i = 0; i < TM / 2; i++) {
        int gm0 = brow + ty * TM + 2 * i;
        #pragma unroll
        for (int j = 0; j < TN; j++) {
            int gn = bcol + tx * TN + j;
            if (gn >= N) continue;
            float lo = __uint_as_float((unsigned)(acc[i][j] & 0xffffffffull));
            float hi = __uint_as_float((unsigned)(acc[i][j] >> 32));
            if (BIAS) { float bb = bias[gn]; lo += bb; hi += bb; }
            if (RELU) { lo = fmaxf(lo, 0.f); hi = fmaxf(hi, 0.f); }
            if (gm0 < M)     C[(size_t)gm0 * N + gn]       = lo;
            if (gm0 + 1 < M) C[(size_t)(gm0 + 1) * N + gn] = hi;
        }
    }
}

// ---------------- layer-3 fused dot: h3p[v] = relu(agg2[v,:]+b2) . W3 -----
__global__ void k_dot3(const float* __restrict__ b2, const float* __restrict__ W3) {
    int gtid = blockIdx.x * blockDim.x + threadIdx.x;
    int v    = gtid >> 5;
    int lane = gtid & 31;
    if (v >= NN) return;
    const float* a = g_agg2 + (size_t)v * F2;
    float s = 0.f;
    for (int f = lane; f < F2; f += 32)
        s += fmaxf(a[f] + b2[f], 0.f) * W3[f];
    #pragma unroll
    for (int o = 16; o > 0; o >>= 1)
        s += __shfl_xor_sync(0xffffffffu, s, o);
    if (lane == 0) g_h3p[v] = s;
}

// out[v] = dis^2*h3p[v] + sum_in norm*h3p[row] + b3   (CSR, no atomics)
__global__ void k_out_csr(float* __restrict__ out, const float* __restrict__ b3) {
    int v = blockIdx.x * blockDim.x + threadIdx.x;
    if (v >= NN) return;
    float d = g_dis[v];
    float s = d * d * g_h3p[v];
    int b  = g_soff[v];
    int e2 = g_soff[v + 1];
    for (int j = b; j < e2; j++) {
        uint2 pe = g_sedge[j];
        s += __uint_as_float(pe.y) * g_h3p[pe.x];
    }
    out[v] = s + b3[0];
}

// ---------------- launch ----------------
extern "C" void kernel_launch(void* const* d_in, const int* in_sizes, int n_in,
                              void* d_out, int out_size) {
    const float* x  = (const float*)d_in[0];
    const int*   ei = (const int*)d_in[1];
    const float* W1 = (const float*)d_in[2];
    const float* b1 = (const float*)d_in[3];
    const float* W2 = (const float*)d_in[4];
    const float* b2 = (const float*)d_in[5];
    const float* W3 = (const float*)d_in[6];
    const float* b3 = (const float*)d_in[7];
    float* out = (float*)d_out;

    const int T = 256;
    float* agg1 = nullptr; cudaGetSymbolAddress((void**)&agg1, g_agg1);
    float* h1   = nullptr; cudaGetSymbolAddress((void**)&h1,   g_h1);
    float* h2p  = nullptr; cudaGetSymbolAddress((void**)&h2p,  g_h2p);
    float* agg2 = nullptr; cudaGetSymbolAddress((void**)&agg2, g_agg2);

    // CSR build (parallel 3-phase scan)
    k_zero_indeg<<<(NN + T - 1) / T, T>>>();
    k_edge_prep<<<(NE + T - 1) / T, T>>>(ei);
    k_dis<<<(NN + T - 1) / T, T>>>();
    k_scan_local<<<NB, 1024>>>();
    k_scan_bsum<<<1, 32>>>();
    k_scan_add<<<NB, 1024>>>();
    k_scatter<<<(NE + T - 1) / T, T>>>();

    const unsigned aggGrid = (unsigned)(((long long)NN * 32 + T - 1) / T);

    // Layer 1: aggregate x (58 feats) first, then GEMM(+bias+relu)
    k_agg_csr<F0><<<aggGrid, T>>>(x, agg1);
    {
        dim3 grid((F1 + 63) / 64, (NN + 127) / 128);
        k_gemm2<128, 64, 16, 8, 8, 128, true, true>
            <<<grid, 128>>>(agg1, W1, b1, h1, NN, F1, F0);
    }

    // Layer 2: GEMM first (300->100), then aggregate 100 feats
    {
        dim3 grid(1, (NN + 127) / 128);   // N=100 fits one 128-col block
        k_gemm2<128, 128, 16, 8, 8, 256, false, false>
            <<<grid, 256>>>(h1, W2, nullptr, h2p, NN, F2, F1);
    }
    k_agg_csr<F2><<<aggGrid, T>>>(h2p, agg2);

    // Layer 3: fused bias2+relu+dot(W3), then CSR aggregation to output
    k_dot3<<<aggGrid, T>>>(b2, W3);
    k_out_csr<<<(NN + T - 1) / T, T>>>(out, b3);

    (void)in_sizes; (void)n_in; (void)out_size;
}